// round 7
// baseline (speedup 1.0000x reference)
#include <cuda_runtime.h>
#include <cstdint>

// ---------------------------------------------------------------------------
// Problem constants
// ---------------------------------------------------------------------------
constexpr int kE = 32, kD = 2048, kF = 768, kT = 2048;
constexpr int k2F = 2 * kF;                       // 1536

constexpr int BM = 128, BN = 128, BK = 32;
constexpr int STAGES = 3;
constexpr int NTHREADS = 128;                     // 4 warps, 2x2, warp tile 64x64

// smem geometry (floats).
// A_LD = 40 (== 8 mod 32): LDS.64 A-fragment loads conflict-free per 16-lane phase.
// B_LD = 136 (== 8 mod 32): LDS.32 B loads conflict-free.
constexpr int A_LD = 40, B_LD = 136;
constexpr int A_F = BM * A_LD;                    // 5120
constexpr int B_F = BK * B_LD;                    // 4352
constexpr int STAGE_F = A_F + B_F;                // 9472 floats
constexpr int SMEM_BYTES = STAGES * STAGE_F * 4;  // 113664 B -> 2 CTA/SM (227KB)

// Scratch (device globals; no allocations allowed)
__device__ float g_Xr    [(size_t)kT * kD];        // X, tf32-rounded, k-octet-permuted
__device__ float g_Wgur  [(size_t)kE * kD * k2F];  // Wgu, tf32-rounded
__device__ float g_Wdr   [(size_t)kE * kF * kD];   // Wd,  tf32-rounded
__device__ float g_gateup[(size_t)kE * kT * k2F];  // raw gate_up
__device__ float g_gated [(size_t)kE * kT * kF];   // rw*up*silu(gate), rounded+permuted

// ---------------------------------------------------------------------------
// helpers
// ---------------------------------------------------------------------------
__device__ __forceinline__ uint32_t smem_u32(const void* p) {
    uint32_t a;
    asm("{ .reg .u64 t; cvta.to.shared.u64 t, %1; cvt.u32.u64 %0, t; }"
        : "=r"(a) : "l"(p));
    return a;
}
__device__ __forceinline__ float to_tf32(float x) {
    float r; asm("cvt.rna.tf32.f32 %0, %1;" : "=f"(r) : "f"(x)); return r;
}
__device__ __forceinline__ float4 round4(float4 v) {
    v.x = to_tf32(v.x); v.y = to_tf32(v.y);
    v.z = to_tf32(v.z); v.w = to_tf32(v.w);
    return v;
}
__device__ __forceinline__ void cp16(uint32_t saddr, const float* g) {
    asm volatile("cp.async.cg.shared.global [%0], [%1], 16;" :: "r"(saddr), "l"(g));
}
#define CP_COMMIT() asm volatile("cp.async.commit_group;" ::: "memory")
#define CP_WAIT1()  asm volatile("cp.async.wait_group 1;" ::: "memory")

__device__ __forceinline__ void mma8(float* c, const uint32_t* a, const uint32_t* b) {
    asm volatile(
        "mma.sync.aligned.m16n8k8.row.col.f32.tf32.tf32.f32 "
        "{%0,%1,%2,%3}, {%4,%5,%6,%7}, {%8,%9}, {%0,%1,%2,%3};"
        : "+f"(c[0]), "+f"(c[1]), "+f"(c[2]), "+f"(c[3])
        : "r"(a[0]), "r"(a[1]), "r"(a[2]), "r"(a[3]), "r"(b[0]), "r"(b[1]));
}

// Octet interleave for A-operand storage: orig cols (j, j+4) -> adjacent pair.
__device__ __forceinline__ void perm_store8(float* dst, const float* o) {
    *(float4*)(dst)     = make_float4(o[0], o[4], o[1], o[5]);
    *(float4*)(dst + 4) = make_float4(o[2], o[6], o[3], o[7]);
}

// ---------------------------------------------------------------------------
// GEMM core: C[128x128] tile, 4 warps in 2(m) x 2(n), warp tile 64x64.
// A smem [BM][A_LD]: k contiguous, octet-permuted. B smem [BK][B_LD]: n contig.
// All values pre-rounded to tf32 -> raw bits feed mma (no cvt in loop).
// ---------------------------------------------------------------------------
struct WarpCtx { int wm, wn, g, tig; };

__device__ __forceinline__ void compute_stage(const float* As, const float* Bs,
                                              const WarpCtx& w, float c[4][8][4]) {
#pragma unroll
    for (int kk = 0; kk < BK; kk += 8) {
        uint32_t a[4][4];
#pragma unroll
        for (int mi = 0; mi < 4; ++mi) {
            const int r = w.wm + 16 * mi + w.g;
            const float2 v0 = *(const float2*)&As[r * A_LD + kk + 2 * w.tig];
            const float2 v1 = *(const float2*)&As[(r + 8) * A_LD + kk + 2 * w.tig];
            a[mi][0] = __float_as_uint(v0.x);
            a[mi][1] = __float_as_uint(v1.x);
            a[mi][2] = __float_as_uint(v0.y);
            a[mi][3] = __float_as_uint(v1.y);
        }
        uint32_t b[8][2];
#pragma unroll
        for (int nj = 0; nj < 8; ++nj) {
            const int col = w.wn + 8 * nj + w.g;
            b[nj][0] = __float_as_uint(Bs[(kk + w.tig) * B_LD + col]);
            b[nj][1] = __float_as_uint(Bs[(kk + w.tig + 4) * B_LD + col]);
        }
#pragma unroll
        for (int mi = 0; mi < 4; ++mi)
#pragma unroll
            for (int nj = 0; nj < 8; ++nj)
                mma8(c[mi][nj], a[mi], b[nj]);
    }
}

// ---------------------------------------------------------------------------
// Pre-pass kernels
// ---------------------------------------------------------------------------
__global__ __launch_bounds__(256)
void prep_X(const float* __restrict__ X) {
    const size_t off = ((size_t)blockIdx.x * 256 + threadIdx.x) * 8;
    float4 x0 = round4(*(const float4*)(X + off));
    float4 x1 = round4(*(const float4*)(X + off + 4));
    float o[8] = { x0.x, x0.y, x0.z, x0.w, x1.x, x1.y, x1.z, x1.w };
    perm_store8(g_Xr + off, o);
}
__global__ __launch_bounds__(256)
void prep_Wgu(const float* __restrict__ W) {
    const size_t i4 = ((size_t)blockIdx.x * 256 + threadIdx.x) * 4;
    *(float4*)(g_Wgur + i4) = round4(*(const float4*)(W + i4));
}
__global__ __launch_bounds__(256)
void prep_Wd(const float* __restrict__ W) {
    const size_t i4 = ((size_t)blockIdx.x * 256 + threadIdx.x) * 4;
    *(float4*)(g_Wdr + i4) = round4(*(const float4*)(W + i4));
}

// ---------------------------------------------------------------------------
// GEMM1: g_gateup[e][t][n] = Xr[t][:] @ Wgur[e][:][n]
// grid (16, 12, 32), 128 threads
// ---------------------------------------------------------------------------
__global__ __launch_bounds__(NTHREADS, 2)
void moe_gemm1() {
    extern __shared__ float sm[];
    const int tid = threadIdx.x;
    const int m0 = blockIdx.x * BM, n0 = blockIdx.y * BN, e = blockIdx.z;
    const float* We = g_Wgur + (size_t)e * kD * k2F;
    const uint32_t sb = smem_u32(sm);

    // cp.async: A one row/thread (8 chunks); B 4 thr/row, 32 cols each (8 chunks)
    const int brow = tid >> 2, bseg = (tid & 3) * 32;
    const float* gA = g_Xr + (size_t)(m0 + tid) * kD;
    const float* gB = We + (size_t)brow * k2F + n0 + bseg;

    const int wid = tid >> 5;
    const WarpCtx w = { (wid >> 1) * 64, (wid & 1) * 64, (tid & 31) >> 2, tid & 3 };

    float c[4][8][4];
#pragma unroll
    for (int i = 0; i < 4; ++i)
#pragma unroll
        for (int j = 0; j < 8; ++j)
#pragma unroll
            for (int q = 0; q < 4; ++q) c[i][j][q] = 0.0f;

    constexpr int ITERS = kD / BK;   // 64

    auto issue = [&](int it) {
        const int s = it % STAGES;
        const uint32_t sa = sb + (s * STAGE_F) * 4;
        const uint32_t sbb = sa + A_F * 4;
        const int k0 = it * BK;
#pragma unroll
        for (int q = 0; q < 8; ++q)
            cp16(sa + (tid * A_LD + q * 4) * 4, gA + k0 + q * 4);
#pragma unroll
        for (int q = 0; q < 8; ++q)
            cp16(sbb + (brow * B_LD + bseg + q * 4) * 4,
                 gB + (size_t)k0 * k2F + q * 4);
    };

    issue(0); CP_COMMIT();
    issue(1); CP_COMMIT();

    for (int it = 0; it < ITERS; ++it) {
        CP_WAIT1();
        __syncthreads();
        if (it + 2 < ITERS) issue(it + 2);
        CP_COMMIT();
        const float* As = sm + (it % STAGES) * STAGE_F;
        compute_stage(As, As + A_F, w, c);
        // no trailing barrier: next iter's barrier protects stage reuse
    }

    float* Cp = g_gateup + ((size_t)e * kT + m0) * k2F + n0;
#pragma unroll
    for (int mi = 0; mi < 4; ++mi)
#pragma unroll
        for (int nj = 0; nj < 8; ++nj) {
            const int r0 = w.wm + 16 * mi + w.g;
            const int cc = w.wn + 8 * nj + 2 * w.tig;
            *(float2*)(Cp + (size_t)r0 * k2F + cc) = make_float2(c[mi][nj][0], c[mi][nj][1]);
            *(float2*)(Cp + (size_t)(r0 + 8) * k2F + cc) = make_float2(c[mi][nj][2], c[mi][nj][3]);
        }
}

// ---------------------------------------------------------------------------
// Act: g_gated[e][t][f] = round_tf32(rw[t][e] * up * silu(gate)), octet-permuted
// ---------------------------------------------------------------------------
__global__ __launch_bounds__(256)
void moe_act(const float* __restrict__ RW) {
    constexpr int NO = kF / 8;                         // 96 octets per (e,t)
    const size_t idx = (size_t)blockIdx.x * 256 + threadIdx.x;
    const int oct = (int)(idx % NO);
    const size_t rest = idx / NO;
    const int t = (int)(rest % kT);
    const int e = (int)(rest / kT);

    const float rw = RW[(size_t)t * kE + e];
    const float* base = g_gateup + ((size_t)e * kT + t) * k2F + oct * 8;
    const float4 g0 = *(const float4*)(base);
    const float4 g1 = *(const float4*)(base + 4);
    const float4 u0 = *(const float4*)(base + kF);
    const float4 u1 = *(const float4*)(base + kF + 4);

    float o[8];
    const float gt[8] = { g0.x, g0.y, g0.z, g0.w, g1.x, g1.y, g1.z, g1.w };
    const float up[8] = { u0.x, u0.y, u0.z, u0.w, u1.x, u1.y, u1.z, u1.w };
#pragma unroll
    for (int j = 0; j < 8; ++j)
        o[j] = to_tf32(rw * up[j] * (gt[j] / (1.0f + __expf(-gt[j]))));

    perm_store8(g_gated + ((size_t)e * kT + t) * kF + oct * 8, o);
}

// ---------------------------------------------------------------------------
// GEMM2: Out[t][d] = sum_{e,f} g_gated[e][t][f] * Wdr[e][f][d]
// grid (16, 16), 128 threads, K = E*F = 24576 (768 iters)
// ---------------------------------------------------------------------------
__global__ __launch_bounds__(NTHREADS, 2)
void moe_gemm2(float* __restrict__ Out) {
    extern __shared__ float sm[];
    const int tid = threadIdx.x;
    const int m0 = blockIdx.x * BM, n0 = blockIdx.y * BN;
    const uint32_t sb = smem_u32(sm);

    const int brow = tid >> 2, bseg = (tid & 3) * 32;

    const int wid = tid >> 5;
    const WarpCtx w = { (wid >> 1) * 64, (wid & 1) * 64, (tid & 31) >> 2, tid & 3 };

    float c[4][8][4];
#pragma unroll
    for (int i = 0; i < 4; ++i)
#pragma unroll
        for (int j = 0; j < 8; ++j)
#pragma unroll
            for (int q = 0; q < 4; ++q) c[i][j][q] = 0.0f;

    constexpr int ITERS = kE * kF / BK;   // 768
    constexpr int IPEX  = kF / BK;        // 24

    auto issue = [&](int it) {
        const int s = it % STAGES;
        const uint32_t sa = sb + (s * STAGE_F) * 4;
        const uint32_t sbb = sa + A_F * 4;
        const int e   = it / IPEX;
        const int kin = (it - e * IPEX) * BK;
        const float* gA = g_gated + ((size_t)e * kT + m0 + tid) * kF + kin;
        const float* gB = g_Wdr + ((size_t)e * kF + kin + brow) * kD + n0 + bseg;
#pragma unroll
        for (int q = 0; q < 8; ++q)
            cp16(sa + (tid * A_LD + q * 4) * 4, gA + q * 4);
#pragma unroll
        for (int q = 0; q < 8; ++q)
            cp16(sbb + (brow * B_LD + bseg + q * 4) * 4, gB + q * 4);
    };

    issue(0); CP_COMMIT();
    issue(1); CP_COMMIT();

    for (int it = 0; it < ITERS; ++it) {
        CP_WAIT1();
        __syncthreads();
        if (it + 2 < ITERS) issue(it + 2);
        CP_COMMIT();
        const float* As = sm + (it % STAGES) * STAGE_F;
        compute_stage(As, As + A_F, w, c);
    }

    float* Cp = Out + (size_t)m0 * kD + n0;
#pragma unroll
    for (int mi = 0; mi < 4; ++mi)
#pragma unroll
        for (int nj = 0; nj < 8; ++nj) {
            const int r0 = w.wm + 16 * mi + w.g;
            const int cc = w.wn + 8 * nj + 2 * w.tig;
            *(float2*)(Cp + (size_t)r0 * kD + cc) = make_float2(c[mi][nj][0], c[mi][nj][1]);
            *(float2*)(Cp + (size_t)(r0 + 8) * kD + cc) = make_float2(c[mi][nj][2], c[mi][nj][3]);
        }
}

// ---------------------------------------------------------------------------
// kernel_launch
//   0: hidden_states fp32 [T,D]   1: routing_weights fp32 [T,E]
//   2: router_indices (unused)    3: gate_up_proj fp32 [E,D,2F]
//   4: down_proj fp32 [E,F,D]     out: fp32 [T,D]
// ---------------------------------------------------------------------------
extern "C" void kernel_launch(void* const* d_in, const int* in_sizes, int n_in,
                              void* d_out, int out_size)
{
    const float* X   = (const float*)d_in[0];
    const float* RW  = (const float*)d_in[1];
    const float* Wgu = (const float*)d_in[3];
    const float* Wdn = (const float*)d_in[4];
    float* Out = (float*)d_out;

    cudaFuncSetAttribute(moe_gemm1, cudaFuncAttributeMaxDynamicSharedMemorySize, SMEM_BYTES);
    cudaFuncSetAttribute(moe_gemm2, cudaFuncAttributeMaxDynamicSharedMemorySize, SMEM_BYTES);

    prep_X<<<(int)(((size_t)kT * kD / 8) / 256), 256>>>(X);
    prep_Wgu<<<(int)(((size_t)kE * kD * k2F / 4) / 256), 256>>>(Wgu);
    prep_Wd<<<(int)(((size_t)kE * kF * kD / 4) / 256), 256>>>(Wdn);

    moe_gemm1<<<dim3(kT / BM, k2F / BN, kE), NTHREADS, SMEM_BYTES>>>();      // (16,12,32)

    const int actBlocks = (int)(((size_t)kE * kT * (kF / 8)) / 256);         // 24576
    moe_act<<<actBlocks, 256>>>(RW);

    moe_gemm2<<<dim3(kT / BM, kD / BN), NTHREADS, SMEM_BYTES>>>(Out);        // (16,16)
}

// round 8
// speedup vs baseline: 1.0727x; 1.0727x over previous
#include <cuda_runtime.h>
#include <cstdint>

// ---------------------------------------------------------------------------
// Problem constants
// ---------------------------------------------------------------------------
constexpr int kE = 32, kD = 2048, kF = 768, kT = 2048;
constexpr int k2F = 2 * kF;                       // 1536

constexpr int BM = 128, BN = 128, BK = 32;
constexpr int STAGES = 3;
constexpr int NTHREADS = 256;                     // 8 warps, 2(m) x 4(n), warp 64x32

// smem geometry (floats). A_LD=40, B_LD=136 (both == 8 mod 32): all LDS.64/32
// fragment gathers conflict-free.
constexpr int A_LD = 40, B_LD = 136;
constexpr int A_F = BM * A_LD;                    // 5120
constexpr int B_F = BK * B_LD;                    // 4352
constexpr int STAGE_F = A_F + B_F;                // 9472 floats
constexpr int SMEM_BYTES = STAGES * STAGE_F * 4;  // 113664 B -> 2 CTA/SM

// Scratch (device globals; no allocations allowed)
__device__ float g_Xr    [(size_t)kT * kD];        // X: tf32, k-octet-permuted
__device__ float g_Wgur  [(size_t)kE * kD * k2F];  // Wgu: tf32, n-pair-permuted
__device__ float g_Wdr   [(size_t)kE * kF * kD];   // Wd:  tf32, n-pair-permuted
__device__ float g_gateup[(size_t)kE * kT * k2F];  // raw gate_up
__device__ float g_gated [(size_t)kE * kT * kF];   // act output: tf32, k-octet-perm
__device__ float g_part  [(size_t)kT * kD];        // split-K partial for GEMM2 z=1

// ---------------------------------------------------------------------------
// helpers
// ---------------------------------------------------------------------------
__device__ __forceinline__ uint32_t smem_u32(const void* p) {
    uint32_t a;
    asm("{ .reg .u64 t; cvta.to.shared.u64 t, %1; cvt.u32.u64 %0, t; }"
        : "=r"(a) : "l"(p));
    return a;
}
__device__ __forceinline__ float to_tf32(float x) {
    float r; asm("cvt.rna.tf32.f32 %0, %1;" : "=f"(r) : "f"(x)); return r;
}
__device__ __forceinline__ float4 round4(float4 v) {
    v.x = to_tf32(v.x); v.y = to_tf32(v.y);
    v.z = to_tf32(v.z); v.w = to_tf32(v.w);
    return v;
}
__device__ __forceinline__ void cp16(uint32_t saddr, const float* g) {
    asm volatile("cp.async.cg.shared.global [%0], [%1], 16;" :: "r"(saddr), "l"(g));
}
#define CP_COMMIT() asm volatile("cp.async.commit_group;" ::: "memory")
#define CP_WAIT1()  asm volatile("cp.async.wait_group 1;" ::: "memory")

__device__ __forceinline__ void mma8(float* c, const uint32_t* a, const uint32_t* b) {
    asm volatile(
        "mma.sync.aligned.m16n8k8.row.col.f32.tf32.tf32.f32 "
        "{%0,%1,%2,%3}, {%4,%5,%6,%7}, {%8,%9}, {%0,%1,%2,%3};"
        : "+f"(c[0]), "+f"(c[1]), "+f"(c[2]), "+f"(c[3])
        : "r"(a[0]), "r"(a[1]), "r"(a[2]), "r"(a[3]), "r"(b[0]), "r"(b[1]));
}

// Octet interleave for A-operand (k axis): cols (j, j+4) adjacent.
__device__ __forceinline__ void perm_store8(float* dst, const float* o) {
    *(float4*)(dst)     = make_float4(o[0], o[4], o[1], o[5]);
    *(float4*)(dst + 4) = make_float4(o[2], o[6], o[3], o[7]);
}

// ---------------------------------------------------------------------------
// GEMM core: C[128x128], 8 warps in 2(m) x 4(n), warp tile 64x32.
// A smem [BM][A_LD]: k contiguous, octet-permuted.
// B smem [BK][B_LD]: n contiguous, PAIR-permuted within 16-col groups
//   (slot 2i = col i, slot 2i+1 = col i+8)  -> LDS.64 B-fragment loads.
// All values pre-rounded to tf32 -> raw bits feed mma (no cvt in loop).
// ---------------------------------------------------------------------------
struct WarpCtx { int wm, wn, g, tig; };

__device__ __forceinline__ void compute_stage(const float* As, const float* Bs,
                                              const WarpCtx& w, float c[4][4][4]) {
#pragma unroll
    for (int kk = 0; kk < BK; kk += 8) {
        uint32_t a[4][4];
#pragma unroll
        for (int mi = 0; mi < 4; ++mi) {
            const int r = w.wm + 16 * mi + w.g;
            const float2 v0 = *(const float2*)&As[r * A_LD + kk + 2 * w.tig];
            const float2 v1 = *(const float2*)&As[(r + 8) * A_LD + kk + 2 * w.tig];
            a[mi][0] = __float_as_uint(v0.x);
            a[mi][1] = __float_as_uint(v1.x);
            a[mi][2] = __float_as_uint(v0.y);
            a[mi][3] = __float_as_uint(v1.y);
        }
        // B pairs: group0 = cols [wn, wn+16) -> nj 0,1 ; group1 -> nj 2,3
        uint32_t b[4][2];
        {
            const int r0 = (kk + w.tig) * B_LD + w.wn + 2 * w.g;
            const int r1 = (kk + w.tig + 4) * B_LD + w.wn + 2 * w.g;
            const float2 p00 = *(const float2*)&Bs[r0];
            const float2 p10 = *(const float2*)&Bs[r0 + 16];
            const float2 p01 = *(const float2*)&Bs[r1];
            const float2 p11 = *(const float2*)&Bs[r1 + 16];
            b[0][0] = __float_as_uint(p00.x); b[1][0] = __float_as_uint(p00.y);
            b[2][0] = __float_as_uint(p10.x); b[3][0] = __float_as_uint(p10.y);
            b[0][1] = __float_as_uint(p01.x); b[1][1] = __float_as_uint(p01.y);
            b[2][1] = __float_as_uint(p11.x); b[3][1] = __float_as_uint(p11.y);
        }
#pragma unroll
        for (int mi = 0; mi < 4; ++mi)
#pragma unroll
            for (int nj = 0; nj < 4; ++nj)
                mma8(c[mi][nj], a[mi], b[nj]);
    }
}

// ---------------------------------------------------------------------------
// Pre-pass kernels
// ---------------------------------------------------------------------------
__global__ __launch_bounds__(256)
void prep_X(const float* __restrict__ X) {
    const size_t off = ((size_t)blockIdx.x * 256 + threadIdx.x) * 8;
    float4 x0 = round4(*(const float4*)(X + off));
    float4 x1 = round4(*(const float4*)(X + off + 4));
    float o[8] = { x0.x, x0.y, x0.z, x0.w, x1.x, x1.y, x1.z, x1.w };
    perm_store8(g_Xr + off, o);
}

// Round + n-pair-permute a weight matrix row-block: 16 cols per thread.
__device__ __forceinline__ void prep_w16(const float* __restrict__ src,
                                         float* __restrict__ dst) {
    float c[16];
#pragma unroll
    for (int q = 0; q < 16; q += 4) {
        const float4 v = round4(*(const float4*)(src + q));
        c[q] = v.x; c[q + 1] = v.y; c[q + 2] = v.z; c[q + 3] = v.w;
    }
#pragma unroll
    for (int i = 0; i < 8; i += 2)
        *(float4*)(dst + 2 * i) = make_float4(c[i], c[i + 8], c[i + 1], c[i + 9]);
}
__global__ __launch_bounds__(256)
void prep_Wgu(const float* __restrict__ W) {
    constexpr int NG = k2F / 16;                      // 96
    const size_t idx = (size_t)blockIdx.x * 256 + threadIdx.x;
    const int grp = (int)(idx % NG);
    const size_t row = idx / NG;                      // over E*D rows
    prep_w16(W + row * k2F + grp * 16, g_Wgur + row * k2F + grp * 16);
}
__global__ __launch_bounds__(256)
void prep_Wd(const float* __restrict__ W) {
    constexpr int NG = kD / 16;                       // 128
    const size_t idx = (size_t)blockIdx.x * 256 + threadIdx.x;
    const int grp = (int)(idx % NG);
    const size_t row = idx / NG;                      // over E*F rows
    prep_w16(W + row * kD + grp * 16, g_Wdr + row * kD + grp * 16);
}

// ---------------------------------------------------------------------------
// GEMM1: g_gateup[e][t][n] = Xr[t][:] @ Wgur[e][:][n]
// grid (16, 12, 32), 256 threads
// ---------------------------------------------------------------------------
__global__ __launch_bounds__(NTHREADS, 2)
void moe_gemm1() {
    extern __shared__ float sm[];
    const int tid = threadIdx.x;
    const int m0 = blockIdx.x * BM, n0 = blockIdx.y * BN, e = blockIdx.z;
    const float* We = g_Wgur + (size_t)e * kD * k2F;
    const uint32_t sb = smem_u32(sm);

    // cp.async: A 2 thr/row x 16 floats; B 8 thr/row x 16 floats
    const int arow = tid >> 1, acol = (tid & 1) * 16;
    const int brow = tid >> 3, bcol = (tid & 7) * 16;
    const float* gA = g_Xr + (size_t)(m0 + arow) * kD + acol;
    const float* gB = We + (size_t)brow * k2F + n0 + bcol;

    const int wid = tid >> 5;
    const WarpCtx w = { ((wid >> 2)) * 64, (wid & 3) * 32, (tid & 31) >> 2, tid & 3 };

    float c[4][4][4];
#pragma unroll
    for (int i = 0; i < 4; ++i)
#pragma unroll
        for (int j = 0; j < 4; ++j)
#pragma unroll
            for (int q = 0; q < 4; ++q) c[i][j][q] = 0.0f;

    constexpr int ITERS = kD / BK;   // 64

    auto issue = [&](int it) {
        const int s = it % STAGES;
        const uint32_t sa = sb + (s * STAGE_F) * 4;
        const uint32_t sbb = sa + A_F * 4;
        const int k0 = it * BK;
#pragma unroll
        for (int q = 0; q < 4; ++q)
            cp16(sa + (arow * A_LD + acol + q * 4) * 4, gA + k0 + q * 4);
#pragma unroll
        for (int q = 0; q < 4; ++q)
            cp16(sbb + (brow * B_LD + bcol + q * 4) * 4,
                 gB + (size_t)k0 * k2F + q * 4);
    };

    issue(0); CP_COMMIT();
    issue(1); CP_COMMIT();

    for (int it = 0; it < ITERS; ++it) {
        CP_WAIT1();
        __syncthreads();
        if (it + 2 < ITERS) issue(it + 2);
        CP_COMMIT();
        const float* As = sm + (it % STAGES) * STAGE_F;
        compute_stage(As, As + A_F, w, c);
        // single barrier per iter: issue(it+2) touches stage (it-1)%3, already drained
    }

    float* Cp = g_gateup + ((size_t)e * kT + m0) * k2F + n0;
#pragma unroll
    for (int mi = 0; mi < 4; ++mi)
#pragma unroll
        for (int nj = 0; nj < 4; ++nj) {
            const int r0 = w.wm + 16 * mi + w.g;
            const int cc = w.wn + 8 * nj + 2 * w.tig;
            *(float2*)(Cp + (size_t)r0 * k2F + cc) = make_float2(c[mi][nj][0], c[mi][nj][1]);
            *(float2*)(Cp + (size_t)(r0 + 8) * k2F + cc) = make_float2(c[mi][nj][2], c[mi][nj][3]);
        }
}

// ---------------------------------------------------------------------------
// Act: g_gated[e][t][f] = round_tf32(rw[t][e] * up * silu(gate)), k-octet-perm
// ---------------------------------------------------------------------------
__global__ __launch_bounds__(256)
void moe_act(const float* __restrict__ RW) {
    constexpr int NO = kF / 8;                         // 96 octets per (e,t)
    const size_t idx = (size_t)blockIdx.x * 256 + threadIdx.x;
    const int oct = (int)(idx % NO);
    const size_t rest = idx / NO;
    const int t = (int)(rest % kT);
    const int e = (int)(rest / kT);

    const float rw = RW[(size_t)t * kE + e];
    const float* base = g_gateup + ((size_t)e * kT + t) * k2F + oct * 8;
    const float4 g0 = *(const float4*)(base);
    const float4 g1 = *(const float4*)(base + 4);
    const float4 u0 = *(const float4*)(base + kF);
    const float4 u1 = *(const float4*)(base + kF + 4);

    float o[8];
    const float gt[8] = { g0.x, g0.y, g0.z, g0.w, g1.x, g1.y, g1.z, g1.w };
    const float up[8] = { u0.x, u0.y, u0.z, u0.w, u1.x, u1.y, u1.z, u1.w };
#pragma unroll
    for (int j = 0; j < 8; ++j)
        o[j] = to_tf32(rw * up[j] * (gt[j] / (1.0f + __expf(-gt[j]))));

    perm_store8(g_gated + ((size_t)e * kT + t) * kF + oct * 8, o);
}

// ---------------------------------------------------------------------------
// GEMM2 (split-K over experts): z=0 -> experts [0,16) -> Out,
//                               z=1 -> experts [16,32) -> g_part.
// grid (16, 16, 2), 256 threads, 384 K-iters each.
// ---------------------------------------------------------------------------
__global__ __launch_bounds__(NTHREADS, 2)
void moe_gemm2(float* __restrict__ Out) {
    extern __shared__ float sm[];
    const int tid = threadIdx.x;
    const int m0 = blockIdx.x * BM, n0 = blockIdx.y * BN;
    const int ez = blockIdx.z * (kE / 2);
    const uint32_t sb = smem_u32(sm);

    const int arow = tid >> 1, acol = (tid & 1) * 16;
    const int brow = tid >> 3, bcol = (tid & 7) * 16;

    const int wid = tid >> 5;
    const WarpCtx w = { ((wid >> 2)) * 64, (wid & 3) * 32, (tid & 31) >> 2, tid & 3 };

    float c[4][4][4];
#pragma unroll
    for (int i = 0; i < 4; ++i)
#pragma unroll
        for (int j = 0; j < 4; ++j)
#pragma unroll
            for (int q = 0; q < 4; ++q) c[i][j][q] = 0.0f;

    constexpr int IPEX  = kF / BK;                 // 24
    constexpr int ITERS = (kE / 2) * IPEX;         // 384

    auto issue = [&](int it) {
        const int s = it % STAGES;
        const uint32_t sa = sb + (s * STAGE_F) * 4;
        const uint32_t sbb = sa + A_F * 4;
        const int e   = ez + it / IPEX;
        const int kin = (it % IPEX) * BK;
        const float* gA = g_gated + ((size_t)e * kT + m0 + arow) * kF + kin + acol;
        const float* gB = g_Wdr + ((size_t)e * kF + kin + brow) * kD + n0 + bcol;
#pragma unroll
        for (int q = 0; q < 4; ++q)
            cp16(sa + (arow * A_LD + acol + q * 4) * 4, gA + q * 4);
#pragma unroll
        for (int q = 0; q < 4; ++q)
            cp16(sbb + (brow * B_LD + bcol + q * 4) * 4, gB + q * 4);
    };

    issue(0); CP_COMMIT();
    issue(1); CP_COMMIT();

    for (int it = 0; it < ITERS; ++it) {
        CP_WAIT1();
        __syncthreads();
        if (it + 2 < ITERS) issue(it + 2);
        CP_COMMIT();
        const float* As = sm + (it % STAGES) * STAGE_F;
        compute_stage(As, As + A_F, w, c);
    }

    float* Cp = (blockIdx.z == 0 ? Out : g_part) + (size_t)m0 * kD + n0;
#pragma unroll
    for (int mi = 0; mi < 4; ++mi)
#pragma unroll
        for (int nj = 0; nj < 4; ++nj) {
            const int r0 = w.wm + 16 * mi + w.g;
            const int cc = w.wn + 8 * nj + 2 * w.tig;
            *(float2*)(Cp + (size_t)r0 * kD + cc) = make_float2(c[mi][nj][0], c[mi][nj][1]);
            *(float2*)(Cp + (size_t)(r0 + 8) * kD + cc) = make_float2(c[mi][nj][2], c[mi][nj][3]);
        }
}

// Combine split-K halves: Out += g_part
__global__ __launch_bounds__(256)
void moe_add(float* __restrict__ Out) {
    const size_t i4 = ((size_t)blockIdx.x * 256 + threadIdx.x) * 4;
    const float4 a = *(const float4*)(Out + i4);
    const float4 b = *(const float4*)(g_part + i4);
    *(float4*)(Out + i4) = make_float4(a.x + b.x, a.y + b.y, a.z + b.z, a.w + b.w);
}

// ---------------------------------------------------------------------------
// kernel_launch
//   0: hidden_states fp32 [T,D]   1: routing_weights fp32 [T,E]
//   2: router_indices (unused)    3: gate_up_proj fp32 [E,D,2F]
//   4: down_proj fp32 [E,F,D]     out: fp32 [T,D]
// ---------------------------------------------------------------------------
extern "C" void kernel_launch(void* const* d_in, const int* in_sizes, int n_in,
                              void* d_out, int out_size)
{
    const float* X   = (const float*)d_in[0];
    const float* RW  = (const float*)d_in[1];
    const float* Wgu = (const float*)d_in[3];
    const float* Wdn = (const float*)d_in[4];
    float* Out = (float*)d_out;

    cudaFuncSetAttribute(moe_gemm1, cudaFuncAttributeMaxDynamicSharedMemorySize, SMEM_BYTES);
    cudaFuncSetAttribute(moe_gemm2, cudaFuncAttributeMaxDynamicSharedMemorySize, SMEM_BYTES);

    prep_X<<<(int)(((size_t)kT * kD / 8) / 256), 256>>>(X);                    // 2048
    prep_Wgu<<<(int)(((size_t)kE * kD * (k2F / 16)) / 256), 256>>>(Wgu);       // 24576
    prep_Wd<<<(int)(((size_t)kE * kF * (kD / 16)) / 256), 256>>>(Wdn);         // 12288

    moe_gemm1<<<dim3(kT / BM, k2F / BN, kE), NTHREADS, SMEM_BYTES>>>();        // (16,12,32)

    const int actBlocks = (int)(((size_t)kE * kT * (kF / 8)) / 256);           // 24576
    moe_act<<<actBlocks, 256>>>(RW);

    moe_gemm2<<<dim3(kT / BM, kD / BN, 2), NTHREADS, SMEM_BYTES>>>(Out);       // (16,16,2)
    moe_add<<<(int)(((size_t)kT * kD / 4) / 256), 256>>>(Out);                 // 4096
}

// round 9
// speedup vs baseline: 2.9737x; 2.7720x over previous
#include <cuda_runtime.h>
#include <cuda_fp16.h>
#include <cstdint>

// ---------------------------------------------------------------------------
// Problem constants
// ---------------------------------------------------------------------------
constexpr int kE = 32, kD = 2048, kF = 768, kT = 2048;
constexpr int k2F = 2 * kF;                       // 1536

constexpr int BM = 128, BN = 128, BK = 64;        // fp16: BK=64 (4 k16-steps)
constexpr int STAGES = 3;
constexpr int NTHREADS = 256;                     // 8 warps, 2(m) x 4(n), warp 64x32

// smem stage: A 128x64 halves (128B rows, swizzled) = 16KB; B 64x128 halves
// (256B rows, per-128B-half swizzled) = 16KB.
constexpr int A_BYTES = BM * BK * 2;              // 16384
constexpr int B_BYTES = BK * BN * 2;              // 16384
constexpr int STAGE_BYTES = A_BYTES + B_BYTES;    // 32768
constexpr int SMEM_BYTES = STAGES * STAGE_BYTES;  // 98304 -> 2 CTA/SM (196KB)

// Scratch (device globals; uint4 arrays for 16B alignment)
__device__ uint4 g_Xh   [(size_t)kT * kD / 8];         // X fp16
__device__ uint4 g_Wguh [(size_t)kE * kD * k2F / 8];   // Wgu fp16
__device__ uint4 g_Wdh  [(size_t)kE * kF * kD / 8];    // Wd fp16
__device__ uint4 g_gatedh[(size_t)kE * kT * kF / 8];   // act output fp16
__device__ float g_gateup[(size_t)kE * kT * k2F];      // raw gate_up fp32
__device__ float g_part  [(size_t)kT * kD];            // split-K partial

// ---------------------------------------------------------------------------
// helpers
// ---------------------------------------------------------------------------
__device__ __forceinline__ uint32_t smem_u32(const void* p) {
    uint32_t a;
    asm("{ .reg .u64 t; cvta.to.shared.u64 t, %1; cvt.u32.u64 %0, t; }"
        : "=r"(a) : "l"(p));
    return a;
}
__device__ __forceinline__ void cp16(uint32_t saddr, const void* g) {
    asm volatile("cp.async.cg.shared.global [%0], [%1], 16;" :: "r"(saddr), "l"(g));
}
#define CP_COMMIT() asm volatile("cp.async.commit_group;" ::: "memory")
#define CP_WAIT1()  asm volatile("cp.async.wait_group 1;" ::: "memory")

__device__ __forceinline__ void ldsm4(uint32_t* r, uint32_t addr) {
    asm volatile("ldmatrix.sync.aligned.m8n8.x4.shared.b16 {%0,%1,%2,%3}, [%4];"
        : "=r"(r[0]), "=r"(r[1]), "=r"(r[2]), "=r"(r[3]) : "r"(addr));
}
__device__ __forceinline__ void ldsm4t(uint32_t* r, uint32_t addr) {
    asm volatile("ldmatrix.sync.aligned.m8n8.x4.trans.shared.b16 {%0,%1,%2,%3}, [%4];"
        : "=r"(r[0]), "=r"(r[1]), "=r"(r[2]), "=r"(r[3]) : "r"(addr));
}
__device__ __forceinline__ void mma16(float* c, const uint32_t* a, const uint32_t* b) {
    asm volatile(
        "mma.sync.aligned.m16n8k16.row.col.f32.f16.f16.f32 "
        "{%0,%1,%2,%3}, {%4,%5,%6,%7}, {%8,%9}, {%0,%1,%2,%3};"
        : "+f"(c[0]), "+f"(c[1]), "+f"(c[2]), "+f"(c[3])
        : "r"(a[0]), "r"(a[1]), "r"(a[2]), "r"(a[3]), "r"(b[0]), "r"(b[1]));
}

__device__ __forceinline__ uint32_t pack2(float x, float y) {
    __half2 h = __floats2half2_rn(x, y);
    return *reinterpret_cast<uint32_t*>(&h);
}

// ---------------------------------------------------------------------------
// Per-thread fragment addressing (precomputed outside K loop)
// A tile: [BM][64] halves, 128B rows, unit (16B) swizzle u^=(row&7).
// B tile: [BK][128] halves, 256B rows, swizzle on each 128B half: inner^=(row&7).
// ---------------------------------------------------------------------------
struct Frag {
    int aRow[4];    // rA*128
    int aMask[4];   // rA&7
    int hi;         // lane>>4 (k+8 selector for A, n+8 selector for B)
    int bOff[2];    // lane-constant byte offset per n16 group
    int g, tig, wm, wn;
};

__device__ __forceinline__ Frag make_frag(int tid) {
    Frag f;
    const int l = tid & 31, wid = tid >> 5;
    f.wm = (wid >> 2) * 64;
    f.wn = (wid & 3) * 32;
    f.g = l >> 2; f.tig = l & 3;
    f.hi = l >> 4;
    const int low8 = l & 7, seg8 = (l >> 3) & 1;
#pragma unroll
    for (int mi = 0; mi < 4; ++mi) {
        const int rA = f.wm + 16 * mi + low8 + 8 * seg8;
        f.aRow[mi] = rA * 128;
        f.aMask[mi] = rA & 7;
    }
#pragma unroll
    for (int p = 0; p < 2; ++p) {
        const int uB = (f.wn >> 3) + 2 * p + f.hi;       // 16B unit within 256B row
        f.bOff[p] = (l & 15) * 256 + ((uB >> 3) << 7) + ((((uB & 7) ^ low8)) << 4);
    }
    return f;
}

__device__ __forceinline__ void compute_stage(uint32_t As, uint32_t Bs,
                                              const Frag& f, float c[4][4][4]) {
#pragma unroll
    for (int ks = 0; ks < 4; ++ks) {             // k16 steps; kk = 16*ks halves
        const int kkU = 2 * ks;                  // 16B units per 16 halves
        uint32_t a[4][4];
#pragma unroll
        for (int mi = 0; mi < 4; ++mi)
            ldsm4(a[mi], As + f.aRow[mi] + (((kkU + f.hi) ^ f.aMask[mi]) << 4));
        uint32_t rb[2][4];
#pragma unroll
        for (int p = 0; p < 2; ++p)
            ldsm4t(rb[p], Bs + (16 * ks) * 256 + f.bOff[p]);
#pragma unroll
        for (int mi = 0; mi < 4; ++mi)
#pragma unroll
            for (int p = 0; p < 2; ++p) {
                mma16(c[mi][2 * p + 0], a[mi], &rb[p][0]);
                mma16(c[mi][2 * p + 1], a[mi], &rb[p][2]);
            }
    }
}

// cp.async destination offsets (byte), swizzled
__device__ __forceinline__ uint32_t a_dst(int row, int u) {        // u 0..7
    return (uint32_t)(row * 128 + ((u ^ (row & 7)) << 4));
}
__device__ __forceinline__ uint32_t b_dst(int row, int u) {        // u 0..15
    return (uint32_t)(row * 256 + ((u >> 3) << 7) + ((((u & 7) ^ (row & 7))) << 4));
}

// ---------------------------------------------------------------------------
// Pre-pass: fp32 -> fp16 conversion (plain layout)
// ---------------------------------------------------------------------------
__device__ __forceinline__ void conv8(const float* src, uint4* dst) {
    const float4 a = *(const float4*)(src);
    const float4 b = *(const float4*)(src + 4);
    uint4 o;
    o.x = pack2(a.x, a.y); o.y = pack2(a.z, a.w);
    o.z = pack2(b.x, b.y); o.w = pack2(b.z, b.w);
    *dst = o;
}
__global__ __launch_bounds__(256) void prep_X(const float* __restrict__ X) {
    const size_t i = (size_t)blockIdx.x * 256 + threadIdx.x;
    conv8(X + i * 8, g_Xh + i);
}
__global__ __launch_bounds__(256) void prep_Wgu(const float* __restrict__ W) {
    const size_t i = (size_t)blockIdx.x * 256 + threadIdx.x;
    conv8(W + i * 8, g_Wguh + i);
}
__global__ __launch_bounds__(256) void prep_Wd(const float* __restrict__ W) {
    const size_t i = (size_t)blockIdx.x * 256 + threadIdx.x;
    conv8(W + i * 8, g_Wdh + i);
}

// ---------------------------------------------------------------------------
// GEMM1: g_gateup[e][t][n] = Xh[t][:] @ Wguh[e][:][n]
// grid (16, 12, 32), 256 threads, 32 K-iters of BK=64
// ---------------------------------------------------------------------------
__global__ __launch_bounds__(NTHREADS, 2)
void moe_gemm1() {
    extern __shared__ char smem[];
    const int tid = threadIdx.x;
    const int m0 = blockIdx.x * BM, n0 = blockIdx.y * BN, e = blockIdx.z;
    const uint32_t sb = smem_u32(smem);

    const __half* Xh = (const __half*)g_Xh;
    const __half* We = (const __half*)g_Wguh + (size_t)e * kD * k2F;

    // cp.async: A row = tid>>1 (128), units (tid&1)*4+q; B row = tid>>2 (64), units (tid&3)*4+q
    const int arow = tid >> 1, au = (tid & 1) * 4;
    const int brow = tid >> 2, bu = (tid & 3) * 4;
    const __half* gA = Xh + (size_t)(m0 + arow) * kD + au * 8;
    const __half* gB = We + (size_t)brow * k2F + n0 + bu * 8;

    uint32_t aD[4], bD[4];
#pragma unroll
    for (int q = 0; q < 4; ++q) {
        aD[q] = a_dst(arow, au + q);
        bD[q] = b_dst(brow, bu + q);
    }

    const Frag f = make_frag(tid);
    float c[4][4][4];
#pragma unroll
    for (int i = 0; i < 4; ++i)
#pragma unroll
        for (int j = 0; j < 4; ++j)
#pragma unroll
            for (int q = 0; q < 4; ++q) c[i][j][q] = 0.0f;

    constexpr int ITERS = kD / BK;   // 32

    auto issue = [&](int it) {
        const uint32_t st = sb + (it % STAGES) * STAGE_BYTES;
        const int k0 = it * BK;
#pragma unroll
        for (int q = 0; q < 4; ++q)
            cp16(st + aD[q], gA + k0 + q * 8);
#pragma unroll
        for (int q = 0; q < 4; ++q)
            cp16(st + A_BYTES + bD[q], gB + (size_t)k0 * k2F + q * 8);
    };

    issue(0); CP_COMMIT();
    issue(1); CP_COMMIT();

    for (int it = 0; it < ITERS; ++it) {
        CP_WAIT1();
        __syncthreads();
        if (it + 2 < ITERS) issue(it + 2);
        CP_COMMIT();
        const uint32_t st = sb + (it % STAGES) * STAGE_BYTES;
        compute_stage(st, st + A_BYTES, f, c);
        // single barrier/iter: issue(it+2) touches stage (it-1)%3, already drained
    }

    float* Cp = g_gateup + ((size_t)e * kT + m0) * k2F + n0;
#pragma unroll
    for (int mi = 0; mi < 4; ++mi)
#pragma unroll
        for (int nj = 0; nj < 4; ++nj) {
            const int r0 = f.wm + 16 * mi + f.g;
            const int cc = f.wn + 8 * nj + 2 * f.tig;
            *(float2*)(Cp + (size_t)r0 * k2F + cc) = make_float2(c[mi][nj][0], c[mi][nj][1]);
            *(float2*)(Cp + (size_t)(r0 + 8) * k2F + cc) = make_float2(c[mi][nj][2], c[mi][nj][3]);
        }
}

// ---------------------------------------------------------------------------
// Act: g_gatedh[e][t][f] = fp16(rw[t][e] * up * silu(gate))
// ---------------------------------------------------------------------------
__global__ __launch_bounds__(256)
void moe_act(const float* __restrict__ RW) {
    constexpr int NO = kF / 8;                         // 96 octets per (e,t)
    const size_t idx = (size_t)blockIdx.x * 256 + threadIdx.x;
    const int oct = (int)(idx % NO);
    const size_t rest = idx / NO;
    const int t = (int)(rest % kT);
    const int e = (int)(rest / kT);

    const float rw = RW[(size_t)t * kE + e];
    const float* base = g_gateup + ((size_t)e * kT + t) * k2F + oct * 8;
    const float4 g0 = *(const float4*)(base);
    const float4 g1 = *(const float4*)(base + 4);
    const float4 u0 = *(const float4*)(base + kF);
    const float4 u1 = *(const float4*)(base + kF + 4);

    const float gt[8] = { g0.x, g0.y, g0.z, g0.w, g1.x, g1.y, g1.z, g1.w };
    const float up[8] = { u0.x, u0.y, u0.z, u0.w, u1.x, u1.y, u1.z, u1.w };
    float o[8];
#pragma unroll
    for (int j = 0; j < 8; ++j)
        o[j] = rw * up[j] * (gt[j] / (1.0f + __expf(-gt[j])));

    uint4 ov;
    ov.x = pack2(o[0], o[1]); ov.y = pack2(o[2], o[3]);
    ov.z = pack2(o[4], o[5]); ov.w = pack2(o[6], o[7]);
    g_gatedh[((size_t)e * kT + t) * (kF / 8) + oct] = ov;
}

// ---------------------------------------------------------------------------
// GEMM2 (split-K over experts): z=0 -> experts [0,16) -> Out, z=1 -> g_part.
// grid (16, 16, 2), 256 threads, 192 K-iters of BK=64.
// ---------------------------------------------------------------------------
__global__ __launch_bounds__(NTHREADS, 2)
void moe_gemm2(float* __restrict__ Out) {
    extern __shared__ char smem[];
    const int tid = threadIdx.x;
    const int m0 = blockIdx.x * BM, n0 = blockIdx.y * BN;
    const int ez = blockIdx.z * (kE / 2);
    const uint32_t sb = smem_u32(smem);

    const __half* Ah = (const __half*)g_gatedh;
    const __half* Wh = (const __half*)g_Wdh;

    const int arow = tid >> 1, au = (tid & 1) * 4;
    const int brow = tid >> 2, bu = (tid & 3) * 4;

    uint32_t aD[4], bD[4];
#pragma unroll
    for (int q = 0; q < 4; ++q) {
        aD[q] = a_dst(arow, au + q);
        bD[q] = b_dst(brow, bu + q);
    }

    const Frag f = make_frag(tid);
    float c[4][4][4];
#pragma unroll
    for (int i = 0; i < 4; ++i)
#pragma unroll
        for (int j = 0; j < 4; ++j)
#pragma unroll
            for (int q = 0; q < 4; ++q) c[i][j][q] = 0.0f;

    constexpr int IPEX  = kF / BK;                 // 12
    constexpr int ITERS = (kE / 2) * IPEX;         // 192

    auto issue = [&](int it) {
        const uint32_t st = sb + (it % STAGES) * STAGE_BYTES;
        const int e   = ez + it / IPEX;
        const int kin = (it % IPEX) * BK;
        const __half* gA = Ah + ((size_t)e * kT + m0 + arow) * kF + kin + au * 8;
        const __half* gB = Wh + ((size_t)e * kF + kin + brow) * kD + n0 + bu * 8;
#pragma unroll
        for (int q = 0; q < 4; ++q)
            cp16(st + aD[q], gA + q * 8);
#pragma unroll
        for (int q = 0; q < 4; ++q)
            cp16(st + A_BYTES + bD[q], gB + q * 8);
    };

    issue(0); CP_COMMIT();
    issue(1); CP_COMMIT();

    for (int it = 0; it < ITERS; ++it) {
        CP_WAIT1();
        __syncthreads();
        if (it + 2 < ITERS) issue(it + 2);
        CP_COMMIT();
        const uint32_t st = sb + (it % STAGES) * STAGE_BYTES;
        compute_stage(st, st + A_BYTES, f, c);
    }

    float* Cp = (blockIdx.z == 0 ? Out : g_part) + (size_t)m0 * kD + n0;
#pragma unroll
    for (int mi = 0; mi < 4; ++mi)
#pragma unroll
        for (int nj = 0; nj < 4; ++nj) {
            const int r0 = f.wm + 16 * mi + f.g;
            const int cc = f.wn + 8 * nj + 2 * f.tig;
            *(float2*)(Cp + (size_t)r0 * kD + cc) = make_float2(c[mi][nj][0], c[mi][nj][1]);
            *(float2*)(Cp + (size_t)(r0 + 8) * kD + cc) = make_float2(c[mi][nj][2], c[mi][nj][3]);
        }
}

// Combine split-K halves: Out += g_part
__global__ __launch_bounds__(256)
void moe_add(float* __restrict__ Out) {
    const size_t i4 = ((size_t)blockIdx.x * 256 + threadIdx.x) * 4;
    const float4 a = *(const float4*)(Out + i4);
    const float4 b = *(const float4*)(g_part + i4);
    *(float4*)(Out + i4) = make_float4(a.x + b.x, a.y + b.y, a.z + b.z, a.w + b.w);
}

// ---------------------------------------------------------------------------
// kernel_launch
//   0: hidden_states fp32 [T,D]   1: routing_weights fp32 [T,E]
//   2: router_indices (unused)    3: gate_up_proj fp32 [E,D,2F]
//   4: down_proj fp32 [E,F,D]     out: fp32 [T,D]
// ---------------------------------------------------------------------------
extern "C" void kernel_launch(void* const* d_in, const int* in_sizes, int n_in,
                              void* d_out, int out_size)
{
    const float* X   = (const float*)d_in[0];
    const float* RW  = (const float*)d_in[1];
    const float* Wgu = (const float*)d_in[3];
    const float* Wdn = (const float*)d_in[4];
    float* Out = (float*)d_out;

    cudaFuncSetAttribute(moe_gemm1, cudaFuncAttributeMaxDynamicSharedMemorySize, SMEM_BYTES);
    cudaFuncSetAttribute(moe_gemm2, cudaFuncAttributeMaxDynamicSharedMemorySize, SMEM_BYTES);

    prep_X<<<(int)(((size_t)kT * kD / 8) / 256), 256>>>(X);                    // 2048
    prep_Wgu<<<(int)(((size_t)kE * kD * k2F / 8) / 256), 256>>>(Wgu);          // 49152
    prep_Wd<<<(int)(((size_t)kE * kF * kD / 8) / 256), 256>>>(Wdn);            // 24576

    moe_gemm1<<<dim3(kT / BM, k2F / BN, kE), NTHREADS, SMEM_BYTES>>>();        // (16,12,32)

    const int actBlocks = (int)(((size_t)kE * kT * (kF / 8)) / 256);           // 24576
    moe_act<<<actBlocks, 256>>>(RW);

    moe_gemm2<<<dim3(kT / BM, kD / BN, 2), NTHREADS, SMEM_BYTES>>>(Out);       // (16,16,2)
    moe_add<<<(int)(((size_t)kT * kD / 4) / 256), 256>>>(Out);                 // 4096
}